// round 3
// baseline (speedup 1.0000x reference)
#include <cuda_runtime.h>
#include <math.h>

// Problem constants (match reference)
#define Hc 384
#define Wc 384
#define Bc 4
#define Mc 192
#define EPSc 1e-6f
#define MAXD 543.0580079f        // sqrt(384^2 + 384^2)
#define Cc (EPSc / MAXD)         // EPS / MAX_DIST

// Tiling
#define TPB 192
#define JT 2          // columns per thread: 192*2 = 384 = W
#define RR 6          // rows per block
#define MC 8          // m-chunk (4 packed pairs)
#define TILES (Hc / RR)            // 64 row tiles per image
#define NBLOCKS (Bc * TILES)       // 256 blocks

// Persistent scratch. Zero-init is semantically "+inf" for t2 keys
// (key = 0x7F800000 - bits, atomicMax), and 0 for the arrival counter.
// The finisher block resets both to 0 each call -> deterministic replays.
__device__ int   g_t2key[Bc * Mc];
__device__ float g_t1part[NBLOCKS];
__device__ float g_ppart[NBLOCKS];
__device__ int   g_ctr;

// ---- Blackwell packed fp32x2 helpers ----
__device__ __forceinline__ float2 f2add(float2 a, float2 b) {
    unsigned long long ua = *reinterpret_cast<unsigned long long*>(&a);
    unsigned long long ub = *reinterpret_cast<unsigned long long*>(&b);
    unsigned long long ur;
    asm("add.rn.f32x2 %0, %1, %2;" : "=l"(ur) : "l"(ua), "l"(ub));
    return *reinterpret_cast<float2*>(&ur);
}
__device__ __forceinline__ float2 f2sub(float2 a, float2 b) {
    unsigned long long ua = *reinterpret_cast<unsigned long long*>(&a);
    unsigned long long ub = *reinterpret_cast<unsigned long long*>(&b);
    unsigned long long ur;
    asm("sub.rn.f32x2 %0, %1, %2;" : "=l"(ur) : "l"(ua), "l"(ub));
    return *reinterpret_cast<float2*>(&ur);
}
__device__ __forceinline__ float2 f2mul(float2 a, float2 b) {
    unsigned long long ua = *reinterpret_cast<unsigned long long*>(&a);
    unsigned long long ub = *reinterpret_cast<unsigned long long*>(&b);
    unsigned long long ur;
    asm("mul.rn.f32x2 %0, %1, %2;" : "=l"(ur) : "l"(ua), "l"(ub));
    return *reinterpret_cast<float2*>(&ur);
}

__global__ __launch_bounds__(TPB) void whd_kernel(
    const float* __restrict__ prob,
    const float* __restrict__ gt,
    const float* __restrict__ osz,
    float* __restrict__ out)
{
    const int blk  = blockIdx.x;
    const int b    = blk / TILES;
    const int row0 = (blk % TILES) * RR;
    const int tid  = threadIdx.x;
    const int lane = tid & 31;
    const int wrp  = tid >> 5;

    __shared__ __align__(16) float s_gx[Mc];
    __shared__ __align__(16) float s_dy2[RR * Mc];
    __shared__ float s_red[12];
    __shared__ float4 s_f4[TPB];
    __shared__ int s_last;

    const float fy = osz[b * 2 + 0] * (1.0f / (float)Hc);
    const float fx = osz[b * 2 + 1] * (1.0f / (float)Wc);

    // gt: thread tid owns m = tid (TPB == Mc)
    {
        const float2* gt2 = (const float2*)gt;
        float2 g = gt2[b * Mc + tid];
        float gy = g.x * fy;
        s_gx[tid] = g.y * fx;
#pragma unroll
        for (int k = 0; k < RR; k++) {
            float dy = (float)(row0 + k) * fy - gy;
            s_dy2[k * Mc + tid] = dy * dy;
        }
    }

    // Per-pixel p and 1/w^2 (w = p^4 + EPS/MAX_DIST), duplicated pairs for f32x2
    const float* pimg = prob + b * Hc * Wc;
    float  pr[RR][JT];
    float2 iw2d[RR][JT];
    float2 xjd[JT];
#pragma unroll
    for (int jt = 0; jt < JT; jt++) {
        float xv = (float)(tid + jt * TPB) * fx;
        xjd[jt] = make_float2(xv, xv);
    }
#pragma unroll
    for (int i = 0; i < RR; i++) {
#pragma unroll
        for (int jt = 0; jt < JT; jt++) {
            float p = pimg[(row0 + i) * Wc + tid + jt * TPB];
            pr[i][jt] = p;
            float p2 = p * p;
            float w  = p2 * p2 + Cc;
            float iw = __fdividef(1.0f, w);
            float iw2 = iw * iw;
            iw2d[i][jt] = make_float2(iw2, iw2);
        }
    }
    __syncthreads();

    float pixmin[RR][JT];
#pragma unroll
    for (int i = 0; i < RR; i++)
#pragma unroll
        for (int jt = 0; jt < JT; jt++) pixmin[i][jt] = 3.0e38f;

    const float2* s_gx2  = (const float2*)s_gx;

    for (int m0 = 0; m0 < Mc; m0 += MC) {
        float2 dx2p[JT][MC / 2];
        float2 t2p[MC / 2];
#pragma unroll
        for (int mp = 0; mp < MC / 2; mp++) {
            float2 gxp = s_gx2[(m0 >> 1) + mp];          // broadcast LDS.64
            t2p[mp] = make_float2(3.0e38f, 3.0e38f);
#pragma unroll
            for (int jt = 0; jt < JT; jt++) {
                float2 dxp = f2sub(xjd[jt], gxp);
                dx2p[jt][mp] = f2mul(dxp, dxp);
            }
        }
#pragma unroll
        for (int i = 0; i < RR; i++) {
            const float2* dy2row = (const float2*)(s_dy2 + i * Mc + m0);
#pragma unroll
            for (int mp = 0; mp < MC / 2; mp++) {
                float2 dy2p = dy2row[mp];                 // broadcast LDS.64
#pragma unroll
                for (int jt = 0; jt < JT; jt++) {
                    float2 d2 = f2add(dy2p, dx2p[jt][mp]);
                    float2 t  = f2mul(d2, iw2d[i][jt]);
                    pixmin[i][jt] = fminf(pixmin[i][jt], fminf(d2.x, d2.y));
                    t2p[mp].x = fminf(t2p[mp].x, t.x);
                    t2p[mp].y = fminf(t2p[mp].y, t.y);
                }
            }
        }
        // warp-reduce the 8 per-m mins; one RED.MAX per (warp, m)
        float t2s[MC];
#pragma unroll
        for (int mp = 0; mp < MC / 2; mp++) {
            t2s[2 * mp]     = t2p[mp].x;
            t2s[2 * mp + 1] = t2p[mp].y;
        }
#pragma unroll
        for (int mc = 0; mc < MC; mc++) {
            float v = t2s[mc];
            v = fminf(v, __shfl_xor_sync(0xffffffffu, v, 16));
            v = fminf(v, __shfl_xor_sync(0xffffffffu, v, 8));
            v = fminf(v, __shfl_xor_sync(0xffffffffu, v, 4));
            v = fminf(v, __shfl_xor_sync(0xffffffffu, v, 2));
            v = fminf(v, __shfl_xor_sync(0xffffffffu, v, 1));
            if (lane == mc)
                atomicMax(&g_t2key[b * Mc + m0 + mc],
                          0x7F800000 - __float_as_int(v));
        }
    }

    // term1 partials: sum p * sqrt(min_m d2), and sum p
    float t1p = 0.0f, pp = 0.0f;
#pragma unroll
    for (int i = 0; i < RR; i++) {
#pragma unroll
        for (int jt = 0; jt < JT; jt++) {
            t1p += pr[i][jt] * sqrtf(pixmin[i][jt]);
            pp  += pr[i][jt];
        }
    }
#pragma unroll
    for (int off = 16; off >= 1; off >>= 1) {
        t1p += __shfl_xor_sync(0xffffffffu, t1p, off);
        pp  += __shfl_xor_sync(0xffffffffu, pp,  off);
    }
    if (lane == 0) { s_red[wrp] = t1p; s_red[6 + wrp] = pp; }
    __syncthreads();
    if (tid == 0) {
        float a = 0.0f, c = 0.0f;
#pragma unroll
        for (int w = 0; w < 6; w++) { a += s_red[w]; c += s_red[6 + w]; }
        g_t1part[blk] = a;
        g_ppart[blk]  = c;
    }

    // ---- last-block finalize ----
    __threadfence();
    __syncthreads();
    if (tid == 0) s_last = (atomicAdd(&g_ctr, 1) == NBLOCKS - 1);
    __syncthreads();
    if (!s_last) return;

    // term2: decode, sqrt, clip; per-image sums over m (thread tid <-> m)
    float accb[Bc];
#pragma unroll
    for (int b2 = 0; b2 < Bc; b2++) {
        int k = __ldcg(&g_t2key[b2 * Mc + tid]);
        float v = __int_as_float(0x7F800000 - k);
        accb[b2] = fminf(sqrtf(v), MAXD);
        g_t2key[b2 * Mc + tid] = 0;              // reset for next call
    }
    s_f4[tid] = make_float4(accb[0], accb[1], accb[2], accb[3]);
    __syncthreads();
#pragma unroll
    for (int s = 96; s >= 3; s >>= 1) {          // 192 -> 3
        if (tid < s) {
            float4 a = s_f4[tid], c = s_f4[tid + s];
            s_f4[tid] = make_float4(a.x + c.x, a.y + c.y, a.z + c.z, a.w + c.w);
        }
        __syncthreads();
    }

    // term1: warps 0..3 reduce the 64 block-partials of image = warp id
    __shared__ float s_t1[Bc], s_pp[Bc];
    if (wrp < Bc) {
        float t1 = __ldcg(&g_t1part[wrp * 64 + lane]) +
                   __ldcg(&g_t1part[wrp * 64 + 32 + lane]);
        float ps = __ldcg(&g_ppart [wrp * 64 + lane]) +
                   __ldcg(&g_ppart [wrp * 64 + 32 + lane]);
#pragma unroll
        for (int off = 16; off >= 1; off >>= 1) {
            t1 += __shfl_xor_sync(0xffffffffu, t1, off);
            ps += __shfl_xor_sync(0xffffffffu, ps, off);
        }
        if (lane == 0) { s_t1[wrp] = t1; s_pp[wrp] = ps; }
    }
    __syncthreads();
    if (tid == 0) {
        float4 a = s_f4[0], c = s_f4[1], d = s_f4[2];
        float t2sum[Bc] = { a.x + c.x + d.x, a.y + c.y + d.y,
                            a.z + c.z + d.z, a.w + c.w + d.w };
        float res = 0.0f;
#pragma unroll
        for (int b2 = 0; b2 < Bc; b2++) {
            res += s_t1[b2] / (s_pp[b2] + EPSc);
            res += t2sum[b2] * (1.0f / (float)Mc);
        }
        out[0] = res * (1.0f / (float)Bc);
        g_ctr = 0;                               // reset for next call
    }
}

extern "C" void kernel_launch(void* const* d_in, const int* in_sizes, int n_in,
                              void* d_out, int out_size) {
    const float* prob = (const float*)d_in[0];
    const float* gt   = (const float*)d_in[1];
    const float* osz  = (const float*)d_in[2];
    float* out = (float*)d_out;

    whd_kernel<<<NBLOCKS, TPB>>>(prob, gt, osz, out);
}